// round 1
// baseline (speedup 1.0000x reference)
#include <cuda_runtime.h>
#include <math.h>

#define Bn   64
#define Nn   256
#define Mm   16
#define ONF  92
#define OEF  41
#define NF   128
#define EF   64
#define ROWS (Bn*Nn)   // 16384

// ---- scratch (static device globals; no allocation allowed) ----
__device__ float g_nfA[ROWS*NF];        // 8.4 MB
__device__ float g_nfB[ROWS*NF];        // 8.4 MB
__device__ float g_SG[ROWS*512];        // 33.5 MB : [0:256)=S(+bias), [256:512)=G
__device__ float g_Wce[3*256*OEF];      // combined edge weights per layer
__device__ float g_bce[3*256];
__device__ float g_DA[Nn*Nn];
__device__ float g_fin[ROWS*EF];        // nf after final linear

__device__ __forceinline__ float sigm(float x){
    return __fdividef(1.f, 1.f + __expf(-x));
}
__device__ __forceinline__ float softplusf(float x){
    return fmaxf(x, 0.f) + __logf(1.f + __expf(-fabsf(x)));
}

// ---------------- generic small linear: Y[r,o] = X[r,:]·W[o,:] + b[o] ----------------
template<int IN,int OUT,int RPB>
__global__ void linear_kernel(const float* __restrict__ X, const float* __restrict__ W,
                              const float* __restrict__ bias, float* __restrict__ Y){
    __shared__ float sh[RPB*IN];
    const int rb = blockIdx.x * RPB;
    const int t  = threadIdx.x;                   // 0..OUT-1
    for (int e = t; e < RPB*IN; e += OUT) sh[e] = X[rb*IN + e];
    __syncthreads();
    float acc[RPB];
    #pragma unroll
    for (int r=0;r<RPB;r++) acc[r]=0.f;
    for (int k=0;k<IN;k++){
        float w = W[t*IN+k];
        #pragma unroll
        for (int r=0;r<RPB;r++) acc[r] += sh[r*IN+k]*w;
    }
    float bv = bias[t];
    #pragma unroll
    for (int r=0;r<RPB;r++) Y[(rb+r)*OUT + t] = acc[r] + bv;
}

// -------- precompute Wce[l] = W_l[:,256:320] @ We  and  bce[l] = W_l[:,256:320] @ be --------
__global__ void wce_kernel(const float* __restrict__ W1,const float* __restrict__ W2,
                           const float* __restrict__ W3,const float* __restrict__ We,
                           const float* __restrict__ be){
    const int o = blockIdx.x;       // 0..255
    const int l = blockIdx.y;       // 0..2
    const int t = threadIdx.x;      // 64 threads, use 0..41
    if (t > OEF) return;
    const float* W = (l==0)?W1:((l==1)?W2:W3);
    float acc = 0.f;
    for (int e=0;e<EF;e++){
        float c = W[o*320 + 256 + e];
        float v = (t<OEF) ? We[e*OEF+t] : be[e];
        acc += c*v;
    }
    if (t < OEF) g_Wce[(l*256+o)*OEF + t] = acc;
    else         g_bce[l*256+o] = acc;
}

// -------- DA = sigmoid(DAw*dis + DAb) --------
__global__ void da_kernel(const float* __restrict__ dis,
                          const float* __restrict__ wp, const float* __restrict__ bp){
    int i = blockIdx.x*256 + threadIdx.x;
    g_DA[i] = sigm(wp[0]*dis[i] + bp[0]);
}

// -------- SG GEMM: SG[r, 0:256)   = nf[r]·W[o, 0:128]ᵀ + b[o] + bce[o]
//                   SG[r, 256:512) = nf[r]·W[o,128:256]ᵀ
__global__ void sg_kernel(const float* __restrict__ nf, const float* __restrict__ W,
                          const float* __restrict__ bl, const float* __restrict__ bce){
    __shared__ float Ash[32*64];
    __shared__ float Bsh[64*65];
    const int t  = threadIdx.x;        // 0..255
    const int rb = blockIdx.x * 32;
    const int ob = blockIdx.y * 64;
    const int o_l = t & 63;
    const int rg  = t >> 6;            // 0..3
    float acc[8];
    #pragma unroll
    for (int r=0;r<8;r++) acc[r]=0.f;

    for (int kc=0; kc<128; kc+=64){
        #pragma unroll
        for (int i=0;i<8;i++){                 // A tile 32x64
            int e = t + i*256; int r = e>>6; int kk = e&63;
            Ash[r*64+kk] = nf[(rb+r)*NF + kc + kk];
        }
        #pragma unroll
        for (int i=0;i<16;i++){                // B tile 64x64 (padded)
            int e = t + i*256; int ol = e>>6; int kk = e&63;
            int og = ob + ol;
            float v = (og < 256) ? W[og*320 + kc + kk]
                                 : W[(og-256)*320 + 128 + kc + kk];
            Bsh[ol*65+kk] = v;
        }
        __syncthreads();
        #pragma unroll
        for (int kk=0; kk<64; kk++){
            float w = Bsh[o_l*65+kk];
            #pragma unroll
            for (int r=0;r<8;r++) acc[r] += Ash[(rg*8+r)*64+kk]*w;
        }
        __syncthreads();
    }
    const int og = ob + o_l;
    const float bias = (og < 256) ? (bl[og] + bce[og]) : 0.f;
    #pragma unroll
    for (int r=0;r<8;r++)
        g_SG[(rb+rg*8+r)*512 + og] = acc[r] + bias;
}

// -------- fused conv: per node, 16 edges, gated sigmoid*softplus reduce, node update --------
__global__ __launch_bounds__(128)
void conv_kernel(const float* __restrict__ nf_in, float* __restrict__ nf_out,
                 const float* __restrict__ ef, const int* __restrict__ eidx,
                 const float* __restrict__ Wce, const float* __restrict__ alphap){
    __shared__ float ef_sh[Mm*OEF];
    __shared__ int   idx_sh[Mm];
    const int o = threadIdx.x;         // 0..127 : output feature
    float wF[OEF], wC[OEF];
    #pragma unroll
    for (int k=0;k<OEF;k++){
        wF[k] = Wce[o*OEF + k];            // filter row o
        wC[k] = Wce[(o+128)*OEF + k];      // core   row o+128
    }
    const float alpha = alphap[0];

    const int node0 = blockIdx.x * 8;
    for (int node = node0; node < node0 + 8; node++){
        const int b = node >> 8;
        for (int e = o; e < Mm*OEF; e += 128) ef_sh[e] = ef[node*(Mm*OEF) + e];
        if (o < Mm) idx_sh[o] = eidx[node*Mm + o];
        __syncthreads();

        const float sF = g_SG[node*512 + o];
        const float sC = g_SG[node*512 + 128 + o];
        float acc = 0.f;
        #pragma unroll 1
        for (int m=0;m<Mm;m++){
            int j  = idx_sh[m];
            int jc = (j < 0) ? 0 : j;
            const float* G = g_SG + (size_t)(b*Nn + jc)*512 + 256;
            float gF = sF + G[o];
            float gC = sC + G[128 + o];
            const float* eS = ef_sh + m*OEF;
            #pragma unroll
            for (int k=0;k<OEF;k++){
                float e = eS[k];
                gF += e*wF[k];
                gC += e*wC[k];
            }
            float fil = (j >= 0) ? sigm(gF) : 0.f;
            acc += fil * softplusf(gC);
        }
        float outv = softplusf(alpha * nf_in[node*NF + o] + acc);
        __syncthreads();
        nf_out[node*NF + o] = outv;
    }
}

// -------- output: out[b,i,0:64)=fin, out[b,i,64:128) = sum_j DA[i,j]*fin[b,j,:] --------
__global__ void out_kernel(float* __restrict__ out){
    __shared__ float DS[32*33];
    __shared__ float NS[32*65];
    const int t  = threadIdx.x;       // 256
    const int it = blockIdx.x;        // 0..7 (i tile)
    const int b  = blockIdx.y;        // 0..63
    const int i_l = t & 31;
    const int fg  = t >> 5;           // 0..7
    float acc[8];
    #pragma unroll
    for (int f=0;f<8;f++) acc[f]=0.f;

    for (int jt=0; jt<8; jt++){
        #pragma unroll
        for (int i=0;i<4;i++){
            int e = t + i*256; int r = e>>5; int c = e&31;
            DS[r*33+c] = g_DA[(it*32+r)*Nn + jt*32 + c];
        }
        #pragma unroll
        for (int i=0;i<8;i++){
            int e = t + i*256; int j = e>>6; int f = e&63;
            NS[j*65+f] = g_fin[(b*Nn + jt*32 + j)*EF + f];
        }
        __syncthreads();
        #pragma unroll
        for (int j=0;j<32;j++){
            float d = DS[i_l*33 + j];
            #pragma unroll
            for (int f=0;f<8;f++) acc[f] += d * NS[j*65 + fg*8 + f];
        }
        __syncthreads();
    }
    const int i = it*32 + i_l;
    float* orow = out + (size_t)(b*Nn + i)*128;
    #pragma unroll
    for (int f=0;f<8;f++) orow[64 + fg*8 + f] = acc[f];
    // copy first 64 channels
    for (int e=t; e<32*64; e+=256){
        int r = e>>6; int f = e&63;
        out[(size_t)(b*Nn + it*32 + r)*128 + f] = g_fin[(b*Nn + it*32 + r)*EF + f];
    }
}

extern "C" void kernel_launch(void* const* d_in, const int* in_sizes, int n_in,
                              void* d_out, int out_size){
    const float* node_fea = (const float*)d_in[0];
    const float* edge_fea = (const float*)d_in[1];
    const int*   eidx     = (const int*)  d_in[2];
    const float* dis      = (const float*)d_in[3];
    const float* Wn  = (const float*)d_in[4];
    const float* bn  = (const float*)d_in[5];
    const float* We  = (const float*)d_in[6];
    const float* be  = (const float*)d_in[7];
    const float* W1  = (const float*)d_in[8];
    const float* b1  = (const float*)d_in[9];
    const float* a1  = (const float*)d_in[10];
    const float* W2  = (const float*)d_in[11];
    const float* b2  = (const float*)d_in[12];
    const float* a2  = (const float*)d_in[13];
    const float* W3  = (const float*)d_in[14];
    const float* b3  = (const float*)d_in[15];
    const float* a3  = (const float*)d_in[16];
    const float* Wf  = (const float*)d_in[17];
    const float* bf  = (const float*)d_in[18];
    const float* DAw = (const float*)d_in[19];
    const float* DAb = (const float*)d_in[20];
    float* out = (float*)d_out;

    float *nfA, *nfB, *bceP, *WceP, *finP;
    cudaGetSymbolAddress((void**)&nfA,  g_nfA);
    cudaGetSymbolAddress((void**)&nfB,  g_nfB);
    cudaGetSymbolAddress((void**)&bceP, g_bce);
    cudaGetSymbolAddress((void**)&WceP, g_Wce);
    cudaGetSymbolAddress((void**)&finP, g_fin);

    // node embedding + one-time precomputes
    linear_kernel<ONF,NF,8><<<ROWS/8, NF>>>(node_fea, Wn, bn, nfA);
    wce_kernel<<<dim3(256,3), 64>>>(W1, W2, W3, We, be);
    da_kernel<<<256, 256>>>(dis, DAw, DAb);

    const float* Ws[3] = {W1,W2,W3};
    const float* bs[3] = {b1,b2,b3};
    const float* as[3] = {a1,a2,a3};
    float* nin  = nfA;
    float* nout = nfB;
    for (int l=0; l<3; l++){
        sg_kernel<<<dim3(ROWS/32, 8), 256>>>(nin, Ws[l], bs[l], bceP + l*256);
        conv_kernel<<<ROWS/8, 128>>>(nin, nout, edge_fea, eidx,
                                     WceP + (size_t)l*256*OEF, as[l]);
        float* tmp = nin; nin = nout; nout = tmp;
    }

    linear_kernel<NF,EF,16><<<ROWS/16, EF>>>(nin, Wf, bf, finP);
    out_kernel<<<dim3(8, Bn), 256>>>(out);
}

// round 2
// speedup vs baseline: 1.0062x; 1.0062x over previous
#include <cuda_runtime.h>
#include <math.h>

#define Bn   64
#define Nn   256
#define Mm   16
#define ONF  92
#define OEF  41
#define NF   128
#define EF   64
#define ROWS (Bn*Nn)   // 16384

typedef unsigned long long ull;

// ---- scratch (static device globals; no allocation allowed) ----
__device__ float g_nfA[ROWS*NF];        // 8.4 MB
__device__ float g_nfB[ROWS*NF];        // 8.4 MB
// interleaved layout: [node*512 + 2*o + {0,1}]       = (S_F(o), S_C(o))
//                     [node*512 + 256 + 2*o + {0,1}] = (G_F(o), G_C(o))
__device__ float g_SG[ROWS*512];        // 33.5 MB
__device__ float g_Wce[3*256*OEF];      // folded edge weights per layer
__device__ float g_bce[3*256];
__device__ float g_DA[Nn*Nn];
__device__ float g_fin[ROWS*EF];        // nf after final linear

__device__ __forceinline__ float sigm(float x){
    return __fdividef(1.f, 1.f + __expf(-x));
}
__device__ __forceinline__ float softplusf(float x){
    return fmaxf(x, 0.f) + __logf(1.f + __expf(-fabsf(x)));
}

// ---- packed fp32x2 helpers (sm_103a FFMA2 path) ----
__device__ __forceinline__ ull pack2(float lo, float hi){
    ull r;
    asm("mov.b64 %0, {%1, %2};" : "=l"(r) : "f"(lo), "f"(hi));
    return r;
}
__device__ __forceinline__ void unpack2(ull v, float &lo, float &hi){
    asm("mov.b64 {%0, %1}, %2;" : "=f"(lo), "=f"(hi) : "l"(v));
}
__device__ __forceinline__ void fma2(ull &d, ull a, ull b){
    asm("fma.rn.f32x2 %0, %1, %2, %0;" : "+l"(d) : "l"(a), "l"(b));
}
__device__ __forceinline__ ull add2(ull a, ull b){
    ull r;
    asm("add.rn.f32x2 %0, %1, %2;" : "=l"(r) : "l"(a), "l"(b));
    return r;
}

// ---------------- generic small linear: Y[r,o] = X[r,:]·W[o,:] + b[o] ----------------
template<int IN,int OUT,int RPB>
__global__ void linear_kernel(const float* __restrict__ X, const float* __restrict__ W,
                              const float* __restrict__ bias, float* __restrict__ Y){
    __shared__ float sh[RPB*IN];
    const int rb = blockIdx.x * RPB;
    const int t  = threadIdx.x;                   // 0..OUT-1
    for (int e = t; e < RPB*IN; e += OUT) sh[e] = X[rb*IN + e];
    __syncthreads();
    float acc[RPB];
    #pragma unroll
    for (int r=0;r<RPB;r++) acc[r]=0.f;
    for (int k=0;k<IN;k++){
        float w = W[t*IN+k];
        #pragma unroll
        for (int r=0;r<RPB;r++) acc[r] += sh[r*IN+k]*w;
    }
    float bv = bias[t];
    #pragma unroll
    for (int r=0;r<RPB;r++) Y[(rb+r)*OUT + t] = acc[r] + bv;
}

// -------- precompute Wce[l] = W_l[:,256:320] @ We  and  bce[l] = W_l[:,256:320] @ be --------
__global__ void wce_kernel(const float* __restrict__ W1,const float* __restrict__ W2,
                           const float* __restrict__ W3,const float* __restrict__ We,
                           const float* __restrict__ be){
    const int o = blockIdx.x;       // 0..255
    const int l = blockIdx.y;       // 0..2
    const int t = threadIdx.x;      // 64 threads, use 0..41
    if (t > OEF) return;
    const float* W = (l==0)?W1:((l==1)?W2:W3);
    float acc = 0.f;
    for (int e=0;e<EF;e++){
        float c = W[o*320 + 256 + e];
        float v = (t<OEF) ? We[e*OEF+t] : be[e];
        acc += c*v;
    }
    if (t < OEF) g_Wce[(l*256+o)*OEF + t] = acc;
    else         g_bce[l*256+o] = acc;
}

// -------- DA = sigmoid(DAw*dis + DAb) --------
__global__ void da_kernel(const float* __restrict__ dis,
                          const float* __restrict__ wp, const float* __restrict__ bp){
    int i = blockIdx.x*256 + threadIdx.x;
    g_DA[i] = sigm(wp[0]*dis[i] + bp[0]);
}

// -------- SG GEMM, register-tiled + FFMA2.
// logical col c in 0..511:  c<256 -> S = nf·W[c, 0:128]^T (+bias)
//                           c>=256 -> G = nf·W[c-256, 128:256]^T
// stored interleaved per addr = node*512 + (c&256) + 2*(c&127) + ((c>>7)&1)
__global__ __launch_bounds__(256)
void sg_kernel(const float* __restrict__ nf, const float* __restrict__ W,
               const float* __restrict__ bl, const float* __restrict__ bce){
    __shared__ float Ash[32*64];        // [k][row]  8 KB
    __shared__ ull   Bsh[32*128];       // [k][col] duplicated pairs, 32 KB
    const int t  = threadIdx.x;
    const int rb = blockIdx.x * 64;
    const int cb = blockIdx.y * 128;
    const int cg = t & 31;              // col group: 4 cols
    const int rg = t >> 5;              // row group: 8 rows (4 pairs)

    ull acc[4][4];
    #pragma unroll
    for (int i=0;i<4;i++)
        #pragma unroll
        for (int j=0;j<4;j++) acc[i][j] = 0ULL;

    for (int kt=0; kt<128; kt+=32){
        // stage A: 64 rows x 32 k, transposed into [k][row]
        {
            int ra = t & 63; int q = t >> 6;     // q 0..3
            #pragma unroll
            for (int p=0;p<2;p++){
                int k0 = (q + p*4)*4;
                float4 v = *(const float4*)(nf + (size_t)(rb+ra)*NF + kt + k0);
                Ash[(k0+0)*64+ra]=v.x; Ash[(k0+1)*64+ra]=v.y;
                Ash[(k0+2)*64+ra]=v.z; Ash[(k0+3)*64+ra]=v.w;
            }
        }
        // stage B: 128 cols x 32 k, value-duplicated pairs
        {
            int c = t & 127; int qb = t >> 7;    // qb 0..1
            int og = cb + c;
            const float* Wrow = (og < 256) ? (W + og*320) : (W + (og-256)*320 + 128);
            #pragma unroll
            for (int p=0;p<4;p++){
                int k0 = (qb + p*2)*4;
                float4 v = *(const float4*)(Wrow + kt + k0);
                Bsh[(k0+0)*128+c]=pack2(v.x,v.x); Bsh[(k0+1)*128+c]=pack2(v.y,v.y);
                Bsh[(k0+2)*128+c]=pack2(v.z,v.z); Bsh[(k0+3)*128+c]=pack2(v.w,v.w);
            }
        }
        __syncthreads();
        #pragma unroll 8
        for (int k=0;k<32;k++){
            ulonglong2 a01 = *(const ulonglong2*)(Ash + k*64 + rg*8);     // rows (0,1),(2,3)
            ulonglong2 a23 = *(const ulonglong2*)(Ash + k*64 + rg*8 + 4); // rows (4,5),(6,7)
            ulonglong2 b01 = *(const ulonglong2*)(Bsh + k*128 + cg*4);
            ulonglong2 b23 = *(const ulonglong2*)(Bsh + k*128 + cg*4 + 2);
            fma2(acc[0][0], a01.x, b01.x); fma2(acc[0][1], a01.x, b01.y);
            fma2(acc[0][2], a01.x, b23.x); fma2(acc[0][3], a01.x, b23.y);
            fma2(acc[1][0], a01.y, b01.x); fma2(acc[1][1], a01.y, b01.y);
            fma2(acc[1][2], a01.y, b23.x); fma2(acc[1][3], a01.y, b23.y);
            fma2(acc[2][0], a23.x, b01.x); fma2(acc[2][1], a23.x, b01.y);
            fma2(acc[2][2], a23.x, b23.x); fma2(acc[2][3], a23.x, b23.y);
            fma2(acc[3][0], a23.y, b01.x); fma2(acc[3][1], a23.y, b01.y);
            fma2(acc[3][2], a23.y, b23.x); fma2(acc[3][3], a23.y, b23.y);
        }
        __syncthreads();
    }
    const int row0 = rb + rg*8;
    #pragma unroll
    for (int j=0;j<4;j++){
        int c = cb + cg*4 + j;
        int aoff = (c & 256) + 2*(c & 127) + ((c >> 7) & 1);
        float bias = (c < 256) ? (bl[c] + bce[c]) : 0.f;
        #pragma unroll
        for (int rp=0;rp<4;rp++){
            float lo, hi; unpack2(acc[rp][j], lo, hi);
            g_SG[(size_t)(row0 + 2*rp  )*512 + aoff] = lo + bias;
            g_SG[(size_t)(row0 + 2*rp+1)*512 + aoff] = hi + bias;
        }
    }
}

// -------- fused conv with packed filter/core chains --------
__global__ __launch_bounds__(128,4)
void conv_kernel(const float* __restrict__ nf_in, float* __restrict__ nf_out,
                 const float* __restrict__ ef, const int* __restrict__ eidx,
                 const float* __restrict__ Wce, const float* __restrict__ alphap){
    __shared__ ull ef_sh[Mm*44];       // duplicated edge values, rows padded 41->44
    __shared__ int idx_sh[Mm];
    const int o = threadIdx.x;         // 0..127 : output feature
    ull wP[44];
    #pragma unroll
    for (int k=0;k<44;k++){
        float f = (k<OEF) ? Wce[o*OEF + k]         : 0.f;
        float c = (k<OEF) ? Wce[(o+128)*OEF + k]   : 0.f;
        wP[k] = pack2(f, c);
    }
    // zero the pad slots once (never overwritten by staging)
    if (o < Mm*3){
        int m = o/3, kk = OEF + (o - m*3);
        ef_sh[m*44 + kk] = 0ULL;
    }
    const float alpha = alphap[0];

    const int node0 = blockIdx.x * 8;
    for (int node = node0; node < node0 + 8; node++){
        const int b = node >> 8;
        for (int e = o; e < Mm*OEF; e += 128){
            int m = e / OEF; int k = e - m*OEF;
            float v = ef[(size_t)node*(Mm*OEF) + e];
            ef_sh[m*44 + k] = pack2(v, v);
        }
        if (o < Mm) idx_sh[o] = eidx[node*Mm + o];
        __syncthreads();

        const ull sP = *(const ull*)(g_SG + (size_t)node*512 + 2*o);
        float accum = 0.f;
        int j = idx_sh[0];
        ull gP = *(const ull*)(g_SG + ((size_t)(b*Nn + (j<0?0:j))*512 + 256 + 2*o));
        #pragma unroll 1
        for (int m=0;m<Mm;m++){
            int jn = 0; ull gPn = 0ULL;
            if (m+1 < Mm){
                jn  = idx_sh[m+1];
                gPn = *(const ull*)(g_SG + ((size_t)(b*Nn + (jn<0?0:jn))*512 + 256 + 2*o));
            }
            ull accA = add2(sP, gP);
            ull accB = 0ULL;
            const ulonglong2* eD = (const ulonglong2*)(ef_sh + m*44);
            #pragma unroll
            for (int kk=0;kk<11;kk++){
                ulonglong2 e0 = eD[2*kk];
                ulonglong2 e1 = eD[2*kk+1];
                fma2(accA, e0.x, wP[4*kk+0]);
                fma2(accB, e0.y, wP[4*kk+1]);
                fma2(accA, e1.x, wP[4*kk+2]);
                fma2(accB, e1.y, wP[4*kk+3]);
            }
            ull g = add2(accA, accB);
            float gF, gC; unpack2(g, gF, gC);
            float fil = (j >= 0) ? sigm(gF) : 0.f;
            accum += fil * softplusf(gC);
            j = jn; gP = gPn;
        }
        float outv = softplusf(alpha * nf_in[(size_t)node*NF + o] + accum);
        __syncthreads();
        nf_out[(size_t)node*NF + o] = outv;
    }
}

// -------- output: out[b,i,0:64)=fin, out[b,i,64:128) = sum_j DA[i,j]*fin[b,j,:] --------
__global__ void out_kernel(float* __restrict__ out){
    __shared__ float DS[32*33];
    __shared__ float NS[32*65];
    const int t  = threadIdx.x;       // 256
    const int it = blockIdx.x;        // 0..7 (i tile)
    const int b  = blockIdx.y;        // 0..63
    const int i_l = t & 31;
    const int fg  = t >> 5;           // 0..7
    float acc[8];
    #pragma unroll
    for (int f=0;f<8;f++) acc[f]=0.f;

    for (int jt=0; jt<8; jt++){
        #pragma unroll
        for (int i=0;i<4;i++){
            int e = t + i*256; int r = e>>5; int c = e&31;
            DS[r*33+c] = g_DA[(it*32+r)*Nn + jt*32 + c];
        }
        #pragma unroll
        for (int i=0;i<8;i++){
            int e = t + i*256; int j = e>>6; int f = e&63;
            NS[j*65+f] = g_fin[(b*Nn + jt*32 + j)*EF + f];
        }
        __syncthreads();
        #pragma unroll
        for (int j=0;j<32;j++){
            float d = DS[i_l*33 + j];
            #pragma unroll
            for (int f=0;f<8;f++) acc[f] += d * NS[j*65 + fg*8 + f];
        }
        __syncthreads();
    }
    const int i = it*32 + i_l;
    float* orow = out + (size_t)(b*Nn + i)*128;
    #pragma unroll
    for (int f=0;f<8;f++) orow[64 + fg*8 + f] = acc[f];
    for (int e=t; e<32*64; e+=256){
        int r = e>>6; int f = e&63;
        out[(size_t)(b*Nn + it*32 + r)*128 + f] = g_fin[(b*Nn + it*32 + r)*EF + f];
    }
}

extern "C" void kernel_launch(void* const* d_in, const int* in_sizes, int n_in,
                              void* d_out, int out_size){
    const float* node_fea = (const float*)d_in[0];
    const float* edge_fea = (const float*)d_in[1];
    const int*   eidx     = (const int*)  d_in[2];
    const float* dis      = (const float*)d_in[3];
    const float* Wn  = (const float*)d_in[4];
    const float* bn  = (const float*)d_in[5];
    const float* We  = (const float*)d_in[6];
    const float* be  = (const float*)d_in[7];
    const float* W1  = (const float*)d_in[8];
    const float* b1  = (const float*)d_in[9];
    const float* a1  = (const float*)d_in[10];
    const float* W2  = (const float*)d_in[11];
    const float* b2  = (const float*)d_in[12];
    const float* a2  = (const float*)d_in[13];
    const float* W3  = (const float*)d_in[14];
    const float* b3  = (const float*)d_in[15];
    const float* a3  = (const float*)d_in[16];
    const float* Wf  = (const float*)d_in[17];
    const float* bf  = (const float*)d_in[18];
    const float* DAw = (const float*)d_in[19];
    const float* DAb = (const float*)d_in[20];
    float* out = (float*)d_out;

    float *nfA, *nfB, *bceP, *WceP, *finP;
    cudaGetSymbolAddress((void**)&nfA,  g_nfA);
    cudaGetSymbolAddress((void**)&nfB,  g_nfB);
    cudaGetSymbolAddress((void**)&bceP, g_bce);
    cudaGetSymbolAddress((void**)&WceP, g_Wce);
    cudaGetSymbolAddress((void**)&finP, g_fin);

    linear_kernel<ONF,NF,8><<<ROWS/8, NF>>>(node_fea, Wn, bn, nfA);
    wce_kernel<<<dim3(256,3), 64>>>(W1, W2, W3, We, be);
    da_kernel<<<256, 256>>>(dis, DAw, DAb);

    const float* Ws[3] = {W1,W2,W3};
    const float* bs[3] = {b1,b2,b3};
    const float* as[3] = {a1,a2,a3};
    float* nin  = nfA;
    float* nout = nfB;
    for (int l=0; l<3; l++){
        sg_kernel<<<dim3(ROWS/64, 4), 256>>>(nin, Ws[l], bs[l], bceP + l*256);
        conv_kernel<<<ROWS/8, 128>>>(nin, nout, edge_fea, eidx,
                                     WceP + (size_t)l*256*OEF, as[l]);
        float* tmp = nin; nin = nout; nout = tmp;
    }

    linear_kernel<NF,EF,16><<<ROWS/16, EF>>>(nin, Wf, bf, finP);
    out_kernel<<<dim3(8, Bn), 256>>>(out);
}

// round 3
// speedup vs baseline: 1.0157x; 1.0094x over previous
#include <cuda_runtime.h>
#include <math.h>

#define Bn   64
#define Nn   256
#define Mm   16
#define ONF  92
#define OEF  41
#define NF   128
#define EF   64
#define ROWS (Bn*Nn)   // 16384

typedef unsigned long long ull;

// ---- scratch (static device globals; zero-initialized at load) ----
__device__ float g_nfA[ROWS*NF];
__device__ float g_nfB[ROWS*NF];
// interleaved: [node*512 + 2*o + {0=F,1=C}] = S ; [node*512 + 256 + 2*o + {0,1}] = G
__device__ float g_SG[ROWS*512];
__device__ float g_Wce[3*256*44];      // folded edge weights, rows padded 41->44 (pad stays 0)
__device__ float g_bce[3*256];
__device__ float g_DA[Nn*Nn];
__device__ float g_fin[ROWS*EF];

__device__ __forceinline__ float tanh_ap(float x){
    float r; asm("tanh.approx.f32 %0, %1;" : "=f"(r) : "f"(x)); return r;
}
__device__ __forceinline__ float sigm(float x){          // sigmoid via 1 MUFU
    return fmaf(tanh_ap(0.5f*x), 0.5f, 0.5f);
}
__device__ __forceinline__ float sigm_exact(float x){
    return __fdividef(1.f, 1.f + __expf(-x));
}
__device__ __forceinline__ float softplusf(float x){
    return fmaxf(x, 0.f) + __logf(1.f + __expf(-fabsf(x)));
}

// ---- packed fp32x2 helpers (sm_103a FFMA2 path) ----
__device__ __forceinline__ ull pack2(float lo, float hi){
    ull r; asm("mov.b64 %0, {%1, %2};" : "=l"(r) : "f"(lo), "f"(hi)); return r;
}
__device__ __forceinline__ void unpack2(ull v, float &lo, float &hi){
    asm("mov.b64 {%0, %1}, %2;" : "=f"(lo), "=f"(hi) : "l"(v));
}
__device__ __forceinline__ void fma2(ull &d, ull a, ull b){
    asm("fma.rn.f32x2 %0, %1, %2, %0;" : "+l"(d) : "l"(a), "l"(b));
}
__device__ __forceinline__ ull add2(ull a, ull b){
    ull r; asm("add.rn.f32x2 %0, %1, %2;" : "=l"(r) : "l"(a), "l"(b)); return r;
}

// ---------------- generic small linear: Y[r,o] = X[r,:]·W[o,:] + b[o] ----------------
template<int IN,int OUT,int RPB>
__global__ void linear_kernel(const float* __restrict__ X, const float* __restrict__ W,
                              const float* __restrict__ bias, float* __restrict__ Y){
    __shared__ float sh[RPB*IN];
    const int rb = blockIdx.x * RPB;
    const int t  = threadIdx.x;
    for (int e = t; e < RPB*IN; e += OUT) sh[e] = X[rb*IN + e];
    __syncthreads();
    float acc[RPB];
    #pragma unroll
    for (int r=0;r<RPB;r++) acc[r]=0.f;
    for (int k=0;k<IN;k++){
        float w = W[t*IN+k];
        #pragma unroll
        for (int r=0;r<RPB;r++) acc[r] += sh[r*IN+k]*w;
    }
    float bv = bias[t];
    #pragma unroll
    for (int r=0;r<RPB;r++) Y[(rb+r)*OUT + t] = acc[r] + bv;
}

// -------- precompute Wce[l] = W_l[:,256:320] @ We (rows padded to 44), bce --------
__global__ void wce_kernel(const float* __restrict__ W1,const float* __restrict__ W2,
                           const float* __restrict__ W3,const float* __restrict__ We,
                           const float* __restrict__ be){
    const int o = blockIdx.x;       // 0..255
    const int l = blockIdx.y;       // 0..2
    const int t = threadIdx.x;      // 64 threads, use 0..41
    if (t > OEF) return;
    const float* W = (l==0)?W1:((l==1)?W2:W3);
    float acc = 0.f;
    for (int e=0;e<EF;e++){
        float c = W[o*320 + 256 + e];
        float v = (t<OEF) ? We[e*OEF+t] : be[e];
        acc += c*v;
    }
    if (t < OEF) g_Wce[(l*256+o)*44 + t] = acc;
    else         g_bce[l*256+o] = acc;
}

__global__ void da_kernel(const float* __restrict__ dis,
                          const float* __restrict__ wp, const float* __restrict__ bp){
    int i = blockIdx.x*256 + threadIdx.x;
    g_DA[i] = sigm_exact(wp[0]*dis[i] + bp[0]);
}

// -------- SG GEMM: 128x128 block tile, per-thread 8 rows (4 pairs) x 8 cols, FFMA2 --------
// logical col c: c<256 -> S = nf·W[c,0:128]^T (+bias), c>=256 -> G = nf·W[c-256,128:256]^T
__global__ __launch_bounds__(256,2)
void sg_kernel(const float* __restrict__ nf, const float* __restrict__ W,
               const float* __restrict__ bl, const float* __restrict__ bce){
    __shared__ float Ash[2][16][128];   // [k][row]
    __shared__ float Bsh[2][16][128];   // [k][col]
    const int t  = threadIdx.x;
    const int rb = blockIdx.x * 128;
    const int cb = blockIdx.y * 128;
    const int tx = t & 15;              // col group: 8 cols
    const int ty = t >> 4;              // row group: 8 rows

    // staging map: thread handles row/col sr, k-slots sq..sq+7 of each 16-chunk
    const int sr = t >> 1;
    const int sq = (t & 1) * 8;
    const float* Arow = nf + (size_t)(rb + sr)*NF + sq;
    const int ogc = cb + sr;
    const float* Brow = (ogc < 256) ? (W + ogc*320 + sq)
                                    : (W + (ogc-256)*320 + 128 + sq);

    float4 pa0 = *(const float4*)(Arow + 0);
    float4 pa1 = *(const float4*)(Arow + 4);
    float4 pb0 = *(const float4*)(Brow + 0);
    float4 pb1 = *(const float4*)(Brow + 4);

    ull acc[4][8];
    #pragma unroll
    for (int p=0;p<4;p++)
        #pragma unroll
        for (int j=0;j<8;j++) acc[p][j] = 0ULL;

    #pragma unroll 1
    for (int kt=0; kt<128; kt+=16){
        const int buf = (kt >> 4) & 1;
        Ash[buf][sq+0][sr]=pa0.x; Ash[buf][sq+1][sr]=pa0.y;
        Ash[buf][sq+2][sr]=pa0.z; Ash[buf][sq+3][sr]=pa0.w;
        Ash[buf][sq+4][sr]=pa1.x; Ash[buf][sq+5][sr]=pa1.y;
        Ash[buf][sq+6][sr]=pa1.z; Ash[buf][sq+7][sr]=pa1.w;
        Bsh[buf][sq+0][sr]=pb0.x; Bsh[buf][sq+1][sr]=pb0.y;
        Bsh[buf][sq+2][sr]=pb0.z; Bsh[buf][sq+3][sr]=pb0.w;
        Bsh[buf][sq+4][sr]=pb1.x; Bsh[buf][sq+5][sr]=pb1.y;
        Bsh[buf][sq+6][sr]=pb1.z; Bsh[buf][sq+7][sr]=pb1.w;
        __syncthreads();
        if (kt + 16 < 128){
            pa0 = *(const float4*)(Arow + kt + 16);
            pa1 = *(const float4*)(Arow + kt + 20);
            pb0 = *(const float4*)(Brow + kt + 16);
            pb1 = *(const float4*)(Brow + kt + 20);
        }
        #pragma unroll 8
        for (int k=0;k<16;k++){
            ulonglong2 a01 = *(const ulonglong2*)&Ash[buf][k][ty*8];
            ulonglong2 a23 = *(const ulonglong2*)&Ash[buf][k][ty*8+4];
            float4 b0 = *(const float4*)&Bsh[buf][k][tx*8];
            float4 b1 = *(const float4*)&Bsh[buf][k][tx*8+4];
            ull bb0=pack2(b0.x,b0.x), bb1=pack2(b0.y,b0.y);
            ull bb2=pack2(b0.z,b0.z), bb3=pack2(b0.w,b0.w);
            ull bb4=pack2(b1.x,b1.x), bb5=pack2(b1.y,b1.y);
            ull bb6=pack2(b1.z,b1.z), bb7=pack2(b1.w,b1.w);
            fma2(acc[0][0],a01.x,bb0); fma2(acc[0][1],a01.x,bb1);
            fma2(acc[0][2],a01.x,bb2); fma2(acc[0][3],a01.x,bb3);
            fma2(acc[0][4],a01.x,bb4); fma2(acc[0][5],a01.x,bb5);
            fma2(acc[0][6],a01.x,bb6); fma2(acc[0][7],a01.x,bb7);
            fma2(acc[1][0],a01.y,bb0); fma2(acc[1][1],a01.y,bb1);
            fma2(acc[1][2],a01.y,bb2); fma2(acc[1][3],a01.y,bb3);
            fma2(acc[1][4],a01.y,bb4); fma2(acc[1][5],a01.y,bb5);
            fma2(acc[1][6],a01.y,bb6); fma2(acc[1][7],a01.y,bb7);
            fma2(acc[2][0],a23.x,bb0); fma2(acc[2][1],a23.x,bb1);
            fma2(acc[2][2],a23.x,bb2); fma2(acc[2][3],a23.x,bb3);
            fma2(acc[2][4],a23.x,bb4); fma2(acc[2][5],a23.x,bb5);
            fma2(acc[2][6],a23.x,bb6); fma2(acc[2][7],a23.x,bb7);
            fma2(acc[3][0],a23.y,bb0); fma2(acc[3][1],a23.y,bb1);
            fma2(acc[3][2],a23.y,bb2); fma2(acc[3][3],a23.y,bb3);
            fma2(acc[3][4],a23.y,bb4); fma2(acc[3][5],a23.y,bb5);
            fma2(acc[3][6],a23.y,bb6); fma2(acc[3][7],a23.y,bb7);
        }
        __syncthreads();
    }
    #pragma unroll
    for (int j=0;j<8;j++){
        const int c = cb + tx*8 + j;
        const int aoff = (c & 256) + 2*(c & 127) + ((c >> 7) & 1);
        const float bias = (c < 256) ? (bl[c] + bce[c]) : 0.f;
        #pragma unroll
        for (int p=0;p<4;p++){
            float lo, hi; unpack2(acc[p][j], lo, hi);
            const int row = rb + ty*8 + 2*p;
            g_SG[(size_t)row*512 + aoff]     = lo + bias;
            g_SG[(size_t)(row+1)*512 + aoff] = hi + bias;
        }
    }
}

// -------- fused conv: thread-pair split (even=filter, odd=core), k-pair FFMA2 --------
#define NPB 8
__global__ __launch_bounds__(256)
void conv_kernel(const float* __restrict__ nf_in, float* __restrict__ nf_out,
                 const float* __restrict__ ef, const int* __restrict__ eidx,
                 const float* __restrict__ Wce, const float* __restrict__ alphap){
    __shared__ float ef_sh[2][Mm][44];
    __shared__ int   idx_sh[2][Mm];
    const int t = threadIdx.x;          // 0..255
    const int o = t >> 1;
    const int chain = t & 1;            // 0=filter, 1=core

    // per-chain weights, packed over k-pairs (rows padded to 44 with zeros)
    ull w2[22];
    const float* wrow = Wce + (o + chain*128)*44;
    #pragma unroll
    for (int i=0;i<22;i++){
        float2 wv = *(const float2*)(wrow + 2*i);
        w2[i] = pack2(wv.x, wv.y);
    }
    const float alpha = alphap[0];
    const int node0 = blockIdx.x * NPB;

    // zero pad slots (cols 41..43) of both buffers
    if (t < 2*Mm*3){
        int bb = t/(Mm*3); int r = t - bb*(Mm*3); int m = r/3; int k = 41 + (r - m*3);
        ef_sh[bb][m][k] = 0.f;
    }
    // stage node0 -> buf 0
    {
        const float* src = ef + (size_t)node0*(Mm*OEF);
        for (int e=t; e<Mm*OEF; e+=256){ int m=e/OEF, k=e-m*OEF; ef_sh[0][m][k]=src[e]; }
        if (t < Mm) idx_sh[0][t] = eidx[node0*Mm + t];
    }
    __syncthreads();

    for (int i=0;i<NPB;i++){
        const int node = node0 + i;
        const int buf  = i & 1;
        const int b    = node >> 8;

        // prefetch next node's ef/idx into regs
        float pf0=0.f, pf1=0.f, pf2=0.f; int pidx=0;
        const bool hasnext = (i+1 < NPB);
        if (hasnext){
            const float* src = ef + (size_t)(node+1)*(Mm*OEF);
            pf0 = src[t]; pf1 = src[t+256];
            if (t+512 < Mm*OEF) pf2 = src[t+512];
            if (t < Mm) pidx = eidx[(node+1)*Mm + t];
        }

        // issue all 16 gathers up front (MLP=16)
        const float* SGb = g_SG + (size_t)b*Nn*512;
        float gva[Mm];
        #pragma unroll
        for (int m=0;m<Mm;m++){
            int j  = idx_sh[buf][m];
            int jc = (j < 0) ? 0 : j;
            gva[m] = SGb[(size_t)jc*512 + 256 + t];
        }
        const float sP = g_SG[(size_t)node*512 + t];

        float accum = 0.f;
        #pragma unroll 1
        for (int m=0;m<Mm;m++){
            ull a0 = 0ULL, a1 = 0ULL;
            const ulonglong2* e2p = (const ulonglong2*)ef_sh[buf][m];
            #pragma unroll
            for (int q=0;q<5;q++){
                ulonglong2 ev  = e2p[2*q];
                ulonglong2 ev2 = e2p[2*q+1];
                fma2(a0, ev.x,  w2[4*q+0]); fma2(a1, ev.y,  w2[4*q+1]);
                fma2(a0, ev2.x, w2[4*q+2]); fma2(a1, ev2.y, w2[4*q+3]);
            }
            { ulonglong2 ev = e2p[10];
              fma2(a0, ev.x, w2[20]); fma2(a1, ev.y, w2[21]); }
            ull s = add2(a0, a1);
            float lo, hi; unpack2(s, lo, hi);
            const float gv = lo + hi + sP + gva[m];
            const int j = idx_sh[buf][m];
            float mine;
            if (chain == 0) mine = (j >= 0) ? sigm(gv) : 0.f;
            else            mine = softplusf(gv);
            float other = __shfl_xor_sync(0xFFFFFFFFu, mine, 1);
            accum += mine * other;      // even: fil*sp ; odd: sp*fil (unused)
        }
        if (chain == 0){
            float outv = softplusf(alpha * nf_in[(size_t)node*NF + o] + accum);
            nf_out[(size_t)node*NF + o] = outv;
        }
        // store prefetched into the other buffer
        if (hasnext){
            const int nb = buf ^ 1;
            { int e=t;     int m=e/OEF, k=e-m*OEF; ef_sh[nb][m][k]=pf0; }
            { int e=t+256; int m=e/OEF, k=e-m*OEF; ef_sh[nb][m][k]=pf1; }
            if (t+512 < Mm*OEF){ int e=t+512; int m=e/OEF, k=e-m*OEF; ef_sh[nb][m][k]=pf2; }
            if (t < Mm) idx_sh[nb][t] = pidx;
        }
        __syncthreads();
    }
}

// -------- output: out[b,i,0:64)=fin, out[b,i,64:128) = sum_j DA[i,j]*fin[b,j,:] --------
__global__ void out_kernel(float* __restrict__ out){
    __shared__ float DS[32*33];
    __shared__ float NS[32*65];
    const int t  = threadIdx.x;       // 256
    const int it = blockIdx.x;        // 0..7
    const int b  = blockIdx.y;        // 0..63
    const int i_l = t & 31;
    const int fg  = t >> 5;
    float acc[8];
    #pragma unroll
    for (int f=0;f<8;f++) acc[f]=0.f;

    for (int jt=0; jt<8; jt++){
        #pragma unroll
        for (int i=0;i<4;i++){
            int e = t + i*256; int r = e>>5; int c = e&31;
            DS[r*33+c] = g_DA[(it*32+r)*Nn + jt*32 + c];
        }
        #pragma unroll
        for (int i=0;i<8;i++){
            int e = t + i*256; int j = e>>6; int f = e&63;
            NS[j*65+f] = g_fin[(b*Nn + jt*32 + j)*EF + f];
        }
        __syncthreads();
        #pragma unroll
        for (int j=0;j<32;j++){
            float d = DS[i_l*33 + j];
            #pragma unroll
            for (int f=0;f<8;f++) acc[f] += d * NS[j*65 + fg*8 + f];
        }
        __syncthreads();
    }
    const int i = it*32 + i_l;
    float* orow = out + (size_t)(b*Nn + i)*128;
    #pragma unroll
    for (int f=0;f<8;f++) orow[64 + fg*8 + f] = acc[f];
    for (int e=t; e<32*64; e+=256){
        int r = e>>6; int f = e&63;
        out[(size_t)(b*Nn + it*32 + r)*128 + f] = g_fin[(b*Nn + it*32 + r)*EF + f];
    }
}

extern "C" void kernel_launch(void* const* d_in, const int* in_sizes, int n_in,
                              void* d_out, int out_size){
    const float* node_fea = (const float*)d_in[0];
    const float* edge_fea = (const float*)d_in[1];
    const int*   eidx     = (const int*)  d_in[2];
    const float* dis      = (const float*)d_in[3];
    const float* Wn  = (const float*)d_in[4];
    const float* bn  = (const float*)d_in[5];
    const float* We  = (const float*)d_in[6];
    const float* be  = (const float*)d_in[7];
    const float* W1  = (const float*)d_in[8];
    const float* b1  = (const float*)d_in[9];
    const float* a1  = (const float*)d_in[10];
    const float* W2  = (const float*)d_in[11];
    const float* b2  = (const float*)d_in[12];
    const float* a2  = (const float*)d_in[13];
    const float* W3  = (const float*)d_in[14];
    const float* b3  = (const float*)d_in[15];
    const float* a3  = (const float*)d_in[16];
    const float* Wf  = (const float*)d_in[17];
    const float* bf  = (const float*)d_in[18];
    const float* DAw = (const float*)d_in[19];
    const float* DAb = (const float*)d_in[20];
    float* out = (float*)d_out;

    float *nfA, *nfB, *bceP, *WceP, *finP;
    cudaGetSymbolAddress((void**)&nfA,  g_nfA);
    cudaGetSymbolAddress((void**)&nfB,  g_nfB);
    cudaGetSymbolAddress((void**)&bceP, g_bce);
    cudaGetSymbolAddress((void**)&WceP, g_Wce);
    cudaGetSymbolAddress((void**)&finP, g_fin);

    linear_kernel<ONF,NF,8><<<ROWS/8, NF>>>(node_fea, Wn, bn, nfA);
    wce_kernel<<<dim3(256,3), 64>>>(W1, W2, W3, We, be);
    da_kernel<<<256, 256>>>(dis, DAw, DAb);

    const float* Ws[3] = {W1,W2,W3};
    const float* bs[3] = {b1,b2,b3};
    const float* as[3] = {a1,a2,a3};
    float* nin  = nfA;
    float* nout = nfB;
    for (int l=0; l<3; l++){
        sg_kernel<<<dim3(ROWS/128, 4), 256>>>(nin, Ws[l], bs[l], bceP + l*256);
        conv_kernel<<<ROWS/NPB, 256>>>(nin, nout, edge_fea, eidx,
                                       WceP + (size_t)l*256*44, as[l]);
        float* tmp = nin; nin = nout; nout = tmp;
    }

    linear_kernel<NF,EF,16><<<ROWS/16, EF>>>(nin, Wf, bf, finP);
    out_kernel<<<dim3(8, Bn), 256>>>(out);
}

// round 4
// speedup vs baseline: 1.0200x; 1.0043x over previous
#include <cuda_runtime.h>
#include <math.h>

#define Bn   64
#define Nn   256
#define Mm   16
#define ONF  92
#define OEF  41
#define NF   128
#define EF   64
#define ROWS (Bn*Nn)   // 16384

typedef unsigned long long ull;

// ---- scratch (static device globals) ----
__device__ float g_nfA[ROWS*NF];
__device__ float g_nfB[ROWS*NF];
// interleaved: [node*512 + 2*o + {0=F,1=C}] = S ; [node*512 + 256 + 2*o + {0,1}] = G
__device__ float g_SG[ROWS*512];
__device__ float g_Wce[3*256*44];      // folded edge weights, rows padded 41->44
__device__ float g_bce[3*256];
__device__ float g_DA[Nn*Nn];
__device__ float g_fin[ROWS*EF];

__device__ __forceinline__ float tanh_ap(float x){
    float r; asm("tanh.approx.f32 %0, %1;" : "=f"(r) : "f"(x)); return r;
}
__device__ __forceinline__ float sigm(float x){
    return fmaf(tanh_ap(0.5f*x), 0.5f, 0.5f);
}
__device__ __forceinline__ float sigm_exact(float x){
    return __fdividef(1.f, 1.f + __expf(-x));
}
__device__ __forceinline__ float softplusf(float x){
    return fmaxf(x, 0.f) + __logf(1.f + __expf(-fabsf(x)));
}

// ---- packed fp32x2 helpers ----
__device__ __forceinline__ ull pack2(float lo, float hi){
    ull r; asm("mov.b64 %0, {%1, %2};" : "=l"(r) : "f"(lo), "f"(hi)); return r;
}
__device__ __forceinline__ void unpack2(ull v, float &lo, float &hi){
    asm("mov.b64 {%0, %1}, %2;" : "=f"(lo), "=f"(hi) : "l"(v));
}
__device__ __forceinline__ void fma2(ull &d, ull a, ull b){
    asm("fma.rn.f32x2 %0, %1, %2, %0;" : "+l"(d) : "l"(a), "l"(b));
}
__device__ __forceinline__ ull add2(ull a, ull b){
    ull r; asm("add.rn.f32x2 %0, %1, %2;" : "=l"(r) : "l"(a), "l"(b)); return r;
}

// ---------------- generic small linear ----------------
template<int IN,int OUT,int RPB>
__global__ void linear_kernel(const float* __restrict__ X, const float* __restrict__ W,
                              const float* __restrict__ bias, float* __restrict__ Y){
    __shared__ float sh[RPB*IN];
    const int rb = blockIdx.x * RPB;
    const int t  = threadIdx.x;
    for (int e = t; e < RPB*IN; e += OUT) sh[e] = X[rb*IN + e];
    __syncthreads();
    float acc[RPB];
    #pragma unroll
    for (int r=0;r<RPB;r++) acc[r]=0.f;
    for (int k=0;k<IN;k++){
        float w = W[t*IN+k];
        #pragma unroll
        for (int r=0;r<RPB;r++) acc[r] += sh[r*IN+k]*w;
    }
    float bv = bias[t];
    #pragma unroll
    for (int r=0;r<RPB;r++) Y[(rb+r)*OUT + t] = acc[r] + bv;
}

// -------- Wce[l] = W_l[:,256:320] @ We (rows padded 44), bce --------
__global__ void wce_kernel(const float* __restrict__ W1,const float* __restrict__ W2,
                           const float* __restrict__ W3,const float* __restrict__ We,
                           const float* __restrict__ be){
    const int o = blockIdx.x;
    const int l = blockIdx.y;
    const int t = threadIdx.x;
    if (t > OEF) return;
    const float* W = (l==0)?W1:((l==1)?W2:W3);
    float acc = 0.f;
    for (int e=0;e<EF;e++){
        float c = W[o*320 + 256 + e];
        float v = (t<OEF) ? We[e*OEF+t] : be[e];
        acc += c*v;
    }
    if (t < OEF) g_Wce[(l*256+o)*44 + t] = acc;
    else         g_bce[l*256+o] = acc;
}

// -------- DA = sigmoid(DAw*dis + DAb), split-grid variant --------
__global__ void da_kernel(const float* __restrict__ dis,
                          const float* __restrict__ wp, const float* __restrict__ bp,
                          int off){
    int i = (blockIdx.x + off)*256 + threadIdx.x;
    g_DA[i] = sigm_exact(wp[0]*dis[i] + bp[0]);
}

// -------- SG GEMM (unchanged from R3) --------
__global__ __launch_bounds__(256,2)
void sg_kernel(const float* __restrict__ nf, const float* __restrict__ W,
               const float* __restrict__ bl, const float* __restrict__ bce){
    __shared__ float Ash[2][16][128];
    __shared__ float Bsh[2][16][128];
    const int t  = threadIdx.x;
    const int rb = blockIdx.x * 128;
    const int cb = blockIdx.y * 128;
    const int tx = t & 15;
    const int ty = t >> 4;

    const int sr = t >> 1;
    const int sq = (t & 1) * 8;
    const float* Arow = nf + (size_t)(rb + sr)*NF + sq;
    const int ogc = cb + sr;
    const float* Brow = (ogc < 256) ? (W + ogc*320 + sq)
                                    : (W + (ogc-256)*320 + 128 + sq);

    float4 pa0 = *(const float4*)(Arow + 0);
    float4 pa1 = *(const float4*)(Arow + 4);
    float4 pb0 = *(const float4*)(Brow + 0);
    float4 pb1 = *(const float4*)(Brow + 4);

    ull acc[4][8];
    #pragma unroll
    for (int p=0;p<4;p++)
        #pragma unroll
        for (int j=0;j<8;j++) acc[p][j] = 0ULL;

    #pragma unroll 1
    for (int kt=0; kt<128; kt+=16){
        const int buf = (kt >> 4) & 1;
        Ash[buf][sq+0][sr]=pa0.x; Ash[buf][sq+1][sr]=pa0.y;
        Ash[buf][sq+2][sr]=pa0.z; Ash[buf][sq+3][sr]=pa0.w;
        Ash[buf][sq+4][sr]=pa1.x; Ash[buf][sq+5][sr]=pa1.y;
        Ash[buf][sq+6][sr]=pa1.z; Ash[buf][sq+7][sr]=pa1.w;
        Bsh[buf][sq+0][sr]=pb0.x; Bsh[buf][sq+1][sr]=pb0.y;
        Bsh[buf][sq+2][sr]=pb0.z; Bsh[buf][sq+3][sr]=pb0.w;
        Bsh[buf][sq+4][sr]=pb1.x; Bsh[buf][sq+5][sr]=pb1.y;
        Bsh[buf][sq+6][sr]=pb1.z; Bsh[buf][sq+7][sr]=pb1.w;
        __syncthreads();
        if (kt + 16 < 128){
            pa0 = *(const float4*)(Arow + kt + 16);
            pa1 = *(const float4*)(Arow + kt + 20);
            pb0 = *(const float4*)(Brow + kt + 16);
            pb1 = *(const float4*)(Brow + kt + 20);
        }
        #pragma unroll 8
        for (int k=0;k<16;k++){
            ulonglong2 a01 = *(const ulonglong2*)&Ash[buf][k][ty*8];
            ulonglong2 a23 = *(const ulonglong2*)&Ash[buf][k][ty*8+4];
            float4 b0 = *(const float4*)&Bsh[buf][k][tx*8];
            float4 b1 = *(const float4*)&Bsh[buf][k][tx*8+4];
            ull bb0=pack2(b0.x,b0.x), bb1=pack2(b0.y,b0.y);
            ull bb2=pack2(b0.z,b0.z), bb3=pack2(b0.w,b0.w);
            ull bb4=pack2(b1.x,b1.x), bb5=pack2(b1.y,b1.y);
            ull bb6=pack2(b1.z,b1.z), bb7=pack2(b1.w,b1.w);
            fma2(acc[0][0],a01.x,bb0); fma2(acc[0][1],a01.x,bb1);
            fma2(acc[0][2],a01.x,bb2); fma2(acc[0][3],a01.x,bb3);
            fma2(acc[0][4],a01.x,bb4); fma2(acc[0][5],a01.x,bb5);
            fma2(acc[0][6],a01.x,bb6); fma2(acc[0][7],a01.x,bb7);
            fma2(acc[1][0],a01.y,bb0); fma2(acc[1][1],a01.y,bb1);
            fma2(acc[1][2],a01.y,bb2); fma2(acc[1][3],a01.y,bb3);
            fma2(acc[1][4],a01.y,bb4); fma2(acc[1][5],a01.y,bb5);
            fma2(acc[1][6],a01.y,bb6); fma2(acc[1][7],a01.y,bb7);
            fma2(acc[2][0],a23.x,bb0); fma2(acc[2][1],a23.x,bb1);
            fma2(acc[2][2],a23.x,bb2); fma2(acc[2][3],a23.x,bb3);
            fma2(acc[2][4],a23.x,bb4); fma2(acc[2][5],a23.x,bb5);
            fma2(acc[2][6],a23.x,bb6); fma2(acc[2][7],a23.x,bb7);
            fma2(acc[3][0],a23.y,bb0); fma2(acc[3][1],a23.y,bb1);
            fma2(acc[3][2],a23.y,bb2); fma2(acc[3][3],a23.y,bb3);
            fma2(acc[3][4],a23.y,bb4); fma2(acc[3][5],a23.y,bb5);
            fma2(acc[3][6],a23.y,bb6); fma2(acc[3][7],a23.y,bb7);
        }
        __syncthreads();
    }
    #pragma unroll
    for (int j=0;j<8;j++){
        const int c = cb + tx*8 + j;
        const int aoff = (c & 256) + 2*(c & 127) + ((c >> 7) & 1);
        const float bias = (c < 256) ? (bl[c] + bce[c]) : 0.f;
        #pragma unroll
        for (int p=0;p<4;p++){
            float lo, hi; unpack2(acc[p][j], lo, hi);
            const int row = rb + ty*8 + 2*p;
            g_SG[(size_t)row*512 + aoff]     = lo + bias;
            g_SG[(size_t)(row+1)*512 + aoff] = hi + bias;
        }
    }
}

// -------- fused conv: register-lean, gather window 4, NPB=16 --------
#define NPB 16
__global__ __launch_bounds__(256,2)
void conv_kernel(const float* __restrict__ nf_in, float* __restrict__ nf_out,
                 const float* __restrict__ ef, const int* __restrict__ eidx,
                 const float* __restrict__ Wce, const float* __restrict__ alphap){
    __shared__ float ef_sh[2][Mm][44];
    __shared__ int   idx_sh[2][Mm];
    const int t = threadIdx.x;          // 0..255
    const int o = t >> 1;
    const int chain = t & 1;            // 0=filter, 1=core

    ull w2[22];
    const float* wrow = Wce + (o + chain*128)*44;
    #pragma unroll
    for (int i=0;i<22;i++){
        float2 wv = *(const float2*)(wrow + 2*i);
        w2[i] = pack2(wv.x, wv.y);
    }
    const float alpha = alphap[0];
    const int node0 = blockIdx.x * NPB;

    // zero pad cols 41..43 of both buffers once
    if (t < 2*Mm*3){
        int bb = t/(Mm*3); int r = t - bb*(Mm*3); int m = r/3; int k = 41 + (r - m*3);
        ef_sh[bb][m][k] = 0.f;
    }
    {   // stage node0 -> buf 0
        const float* src = ef + (size_t)node0*(Mm*OEF);
        for (int e=t; e<Mm*OEF; e+=256){ int m=e/OEF, k=e-m*OEF; ef_sh[0][m][k]=src[e]; }
        if (t < Mm) idx_sh[0][t] = eidx[node0*Mm + t];
    }
    __syncthreads();

    for (int i=0;i<NPB;i++){
        const int node = node0 + i;
        const int buf  = i & 1;
        const int b    = node >> 8;

        float pf0=0.f, pf1=0.f, pf2=0.f; int pidx=0;
        const bool hasnext = (i+1 < NPB);
        if (hasnext){
            const float* src = ef + (size_t)(node+1)*(Mm*OEF);
            pf0 = src[t]; pf1 = src[t+256];
            if (t+512 < Mm*OEF) pf2 = src[t+512];
            if (t < Mm) pidx = eidx[(node+1)*Mm + t];
        }

        const float* base = g_SG + (size_t)b*Nn*512 + 256 + t;
        const float sP = g_SG[(size_t)node*512 + t];

        int jq[4]; float gq[4];
        #pragma unroll
        for (int q=0;q<4;q++){
            jq[q] = idx_sh[buf][q];
            gq[q] = base[(size_t)(jq[q] < 0 ? 0 : jq[q])*512];
        }
        float accum = 0.f;
        #pragma unroll 1
        for (int mb=0; mb<Mm; mb+=4){
            int jn[4]={0,0,0,0}; float gn[4]={0.f,0.f,0.f,0.f};
            if (mb+4 < Mm){
                #pragma unroll
                for (int q=0;q<4;q++){
                    jn[q] = idx_sh[buf][mb+4+q];
                    gn[q] = base[(size_t)(jn[q] < 0 ? 0 : jn[q])*512];
                }
            }
            #pragma unroll
            for (int q=0;q<4;q++){
                ull a0 = 0ULL, a1 = 0ULL;
                const ulonglong2* e2p = (const ulonglong2*)ef_sh[buf][mb+q];
                #pragma unroll
                for (int p=0;p<5;p++){
                    ulonglong2 ev  = e2p[2*p];
                    ulonglong2 ev2 = e2p[2*p+1];
                    fma2(a0, ev.x,  w2[4*p+0]); fma2(a1, ev.y,  w2[4*p+1]);
                    fma2(a0, ev2.x, w2[4*p+2]); fma2(a1, ev2.y, w2[4*p+3]);
                }
                { ulonglong2 ev = e2p[10];
                  fma2(a0, ev.x, w2[20]); fma2(a1, ev.y, w2[21]); }
                float lo, hi; unpack2(add2(a0, a1), lo, hi);
                const float gv = lo + hi + sP + gq[q];
                float mine;
                if (chain == 0) mine = (jq[q] >= 0) ? sigm(gv) : 0.f;
                else            mine = softplusf(gv);
                float other = __shfl_xor_sync(0xFFFFFFFFu, mine, 1);
                accum += mine * other;
            }
            #pragma unroll
            for (int q=0;q<4;q++){ jq[q]=jn[q]; gq[q]=gn[q]; }
        }
        if (chain == 0){
            nf_out[(size_t)node*NF + o] =
                softplusf(alpha * nf_in[(size_t)node*NF + o] + accum);
        }
        if (hasnext){
            const int nb = buf ^ 1;
            { int e=t;     int m=e/OEF, k=e-m*OEF; ef_sh[nb][m][k]=pf0; }
            { int e=t+256; int m=e/OEF, k=e-m*OEF; ef_sh[nb][m][k]=pf1; }
            if (t+512 < Mm*OEF){ int e=t+512; int m=e/OEF, k=e-m*OEF; ef_sh[nb][m][k]=pf2; }
            if (t < Mm) idx_sh[nb][t] = pidx;
        }
        __syncthreads();
    }
}

// -------- output --------
__global__ void out_kernel(float* __restrict__ out){
    __shared__ float DS[32*33];
    __shared__ float NS[32*65];
    const int t  = threadIdx.x;
    const int it = blockIdx.x;
    const int b  = blockIdx.y;
    const int i_l = t & 31;
    const int fg  = t >> 5;
    float acc[8];
    #pragma unroll
    for (int f=0;f<8;f++) acc[f]=0.f;

    for (int jt=0; jt<8; jt++){
        #pragma unroll
        for (int i=0;i<4;i++){
            int e = t + i*256; int r = e>>5; int c = e&31;
            DS[r*33+c] = g_DA[(it*32+r)*Nn + jt*32 + c];
        }
        #pragma unroll
        for (int i=0;i<8;i++){
            int e = t + i*256; int j = e>>6; int f = e&63;
            NS[j*65+f] = g_fin[(b*Nn + jt*32 + j)*EF + f];
        }
        __syncthreads();
        #pragma unroll
        for (int j=0;j<32;j++){
            float d = DS[i_l*33 + j];
            #pragma unroll
            for (int f=0;f<8;f++) acc[f] += d * NS[j*65 + fg*8 + f];
        }
        __syncthreads();
    }
    const int i = it*32 + i_l;
    float* orow = out + (size_t)(b*Nn + i)*128;
    #pragma unroll
    for (int f=0;f<8;f++) orow[64 + fg*8 + f] = acc[f];
    for (int e=t; e<32*64; e+=256){
        int r = e>>6; int f = e&63;
        out[(size_t)(b*Nn + it*32 + r)*128 + f] = g_fin[(b*Nn + it*32 + r)*EF + f];
    }
}

extern "C" void kernel_launch(void* const* d_in, const int* in_sizes, int n_in,
                              void* d_out, int out_size){
    const float* node_fea = (const float*)d_in[0];
    const float* edge_fea = (const float*)d_in[1];
    const int*   eidx     = (const int*)  d_in[2];
    const float* dis      = (const float*)d_in[3];
    const float* Wn  = (const float*)d_in[4];
    const float* bn  = (const float*)d_in[5];
    const float* We  = (const float*)d_in[6];
    const float* be  = (const float*)d_in[7];
    const float* W1  = (const float*)d_in[8];
    const float* b1  = (const float*)d_in[9];
    const float* a1  = (const float*)d_in[10];
    const float* W2  = (const float*)d_in[11];
    const float* b2  = (const float*)d_in[12];
    const float* a2  = (const float*)d_in[13];
    const float* W3  = (const float*)d_in[14];
    const float* b3  = (const float*)d_in[15];
    const float* a3  = (const float*)d_in[16];
    const float* Wf  = (const float*)d_in[17];
    const float* bf  = (const float*)d_in[18];
    const float* DAw = (const float*)d_in[19];
    const float* DAb = (const float*)d_in[20];
    float* out = (float*)d_out;

    float *nfA, *nfB, *bceP, *WceP, *finP;
    cudaGetSymbolAddress((void**)&nfA,  g_nfA);
    cudaGetSymbolAddress((void**)&nfB,  g_nfB);
    cudaGetSymbolAddress((void**)&bceP, g_bce);
    cudaGetSymbolAddress((void**)&WceP, g_Wce);
    cudaGetSymbolAddress((void**)&finP, g_fin);

    const float* Ws[3] = {W1,W2,W3};
    const float* bs[3] = {b1,b2,b3};
    const float* as[3] = {a1,a2,a3};

    // launch order arranged so that launch #6 (ncu -s 5 -c 1) is conv layer 1
    linear_kernel<ONF,NF,8><<<ROWS/8, NF>>>(node_fea, Wn, bn, nfA);   // 1
    wce_kernel<<<dim3(256,3), 64>>>(W1, W2, W3, We, be);              // 2
    sg_kernel<<<dim3(ROWS/128, 4), 256>>>(nfA, W1, b1, bceP);         // 3
    da_kernel<<<128, 256>>>(dis, DAw, DAb, 0);                        // 4
    da_kernel<<<128, 256>>>(dis, DAw, DAb, 128);                      // 5

    float* nin  = nfA;
    float* nout = nfB;
    for (int l=0; l<3; l++){
        if (l > 0)
            sg_kernel<<<dim3(ROWS/128, 4), 256>>>(nin, Ws[l], bs[l], bceP + l*256);
        conv_kernel<<<ROWS/NPB, 256>>>(nin, nout, edge_fea, eidx,     // 6 (l=0)
                                       WceP + (size_t)l*256*44, as[l]);
        float* tmp = nin; nin = nout; nout = tmp;
    }

    linear_kernel<NF,EF,16><<<ROWS/16, EF>>>(nin, Wf, bf, finP);
    out_kernel<<<dim3(8, Bn), 256>>>(out);
}

// round 5
// speedup vs baseline: 1.0219x; 1.0018x over previous
#include <cuda_runtime.h>
#include <math.h>

#define Bn   64
#define Nn   256
#define Mm   16
#define ONF  92
#define OEF  41
#define NF   128
#define EF   64
#define ROWS (Bn*Nn)   // 16384

typedef unsigned long long ull;

// ---- scratch (static device globals) ----
__device__ float g_nfA[ROWS*NF];
__device__ float g_nfB[ROWS*NF];
// planar layout per node (512 floats):
//  [0,128)=S_F  [128,256)=S_C  [256,384)=G_F  [384,512)=G_C
__device__ float g_SG[ROWS*512];
__device__ float g_Wce[3*256*44];      // folded edge weights, rows padded 41->44
__device__ float g_bce[3*256];
__device__ float g_DA[Nn*Nn];
__device__ float g_fin[ROWS*EF];

__device__ __forceinline__ float tanh_ap(float x){
    float r; asm("tanh.approx.f32 %0, %1;" : "=f"(r) : "f"(x)); return r;
}
__device__ __forceinline__ float sigm(float x){
    return fmaf(tanh_ap(0.5f*x), 0.5f, 0.5f);
}
__device__ __forceinline__ float sigm_exact(float x){
    return __fdividef(1.f, 1.f + __expf(-x));
}
__device__ __forceinline__ float softplusf(float x){
    return fmaxf(x, 0.f) + __logf(1.f + __expf(-fabsf(x)));
}

// ---- packed fp32x2 helpers ----
__device__ __forceinline__ ull pack2(float lo, float hi){
    ull r; asm("mov.b64 %0, {%1, %2};" : "=l"(r) : "f"(lo), "f"(hi)); return r;
}
__device__ __forceinline__ void unpack2(ull v, float &lo, float &hi){
    asm("mov.b64 {%0, %1}, %2;" : "=f"(lo), "=f"(hi) : "l"(v));
}
__device__ __forceinline__ void fma2(ull &d, ull a, ull b){
    asm("fma.rn.f32x2 %0, %1, %2, %0;" : "+l"(d) : "l"(a), "l"(b));
}
__device__ __forceinline__ ull add2(ull a, ull b){
    ull r; asm("add.rn.f32x2 %0, %1, %2;" : "=l"(r) : "l"(a), "l"(b)); return r;
}

// ---------------- small linear, smem-staged W + transposed X ----------------
// block = OUT threads, RPB rows per block
template<int IN,int OUT,int RPB>
__global__ void linear_kernel(const float* __restrict__ X, const float* __restrict__ W,
                              const float* __restrict__ bias, float* __restrict__ Y){
    __shared__ float Wsh[IN*(OUT+1)];
    __shared__ __align__(16) float Xsh[IN*RPB];
    const int rb = blockIdx.x * RPB;
    const int t  = threadIdx.x;
    // stage W transposed: Wsh[k*(OUT+1)+o] = W[o*IN+k]  (coalesced reads)
    for (int e = t; e < IN*OUT; e += OUT){
        int o = e / IN, k = e - o*IN;
        Wsh[k*(OUT+1) + o] = W[e];
    }
    // stage X transposed: Xsh[k*RPB+r] = X[(rb+r)*IN+k]
    for (int e = t; e < RPB*IN; e += OUT){
        int r = e / IN, k = e - r*IN;
        Xsh[k*RPB + r] = X[(size_t)(rb+r)*IN + e - r*IN];
    }
    __syncthreads();
    float acc[RPB];
    #pragma unroll
    for (int r=0;r<RPB;r++) acc[r]=0.f;
    #pragma unroll 2
    for (int k=0;k<IN;k++){
        float w = Wsh[k*(OUT+1)+t];
        const float4* xr = (const float4*)(Xsh + k*RPB);
        #pragma unroll
        for (int r4=0;r4<RPB/4;r4++){
            float4 xv = xr[r4];
            acc[4*r4+0] += xv.x*w; acc[4*r4+1] += xv.y*w;
            acc[4*r4+2] += xv.z*w; acc[4*r4+3] += xv.w*w;
        }
    }
    float bv = bias[t];
    #pragma unroll
    for (int r=0;r<RPB;r++) Y[(size_t)(rb+r)*OUT + t] = acc[r] + bv;
}

// -------- Wce[l] = W_l[:,256:320] @ We (rows padded 44), bce --------
__global__ void wce_kernel(const float* __restrict__ W1,const float* __restrict__ W2,
                           const float* __restrict__ W3,const float* __restrict__ We,
                           const float* __restrict__ be){
    const int o = blockIdx.x;
    const int l = blockIdx.y;
    const int t = threadIdx.x;
    if (t > OEF) return;
    const float* W = (l==0)?W1:((l==1)?W2:W3);
    float acc = 0.f;
    for (int e=0;e<EF;e++){
        float c = W[o*320 + 256 + e];
        float v = (t<OEF) ? We[e*OEF+t] : be[e];
        acc += c*v;
    }
    if (t < OEF) g_Wce[(l*256+o)*44 + t] = acc;
    else         g_bce[l*256+o] = acc;
}

__global__ void da_kernel(const float* __restrict__ dis,
                          const float* __restrict__ wp, const float* __restrict__ bp,
                          int off){
    int i = (blockIdx.x + off)*256 + threadIdx.x;
    g_DA[i] = sigm_exact(wp[0]*dis[i] + bp[0]);
}

// -------- SG GEMM (tile as R3; planar output layout) --------
__global__ __launch_bounds__(256,2)
void sg_kernel(const float* __restrict__ nf, const float* __restrict__ W,
               const float* __restrict__ bl, const float* __restrict__ bce){
    __shared__ float Ash[2][16][128];
    __shared__ float Bsh[2][16][128];
    const int t  = threadIdx.x;
    const int rb = blockIdx.x * 128;
    const int cb = blockIdx.y * 128;
    const int tx = t & 15;
    const int ty = t >> 4;

    const int sr = t >> 1;
    const int sq = (t & 1) * 8;
    const float* Arow = nf + (size_t)(rb + sr)*NF + sq;
    const int ogc = cb + sr;
    const float* Brow = (ogc < 256) ? (W + ogc*320 + sq)
                                    : (W + (ogc-256)*320 + 128 + sq);

    float4 pa0 = *(const float4*)(Arow + 0);
    float4 pa1 = *(const float4*)(Arow + 4);
    float4 pb0 = *(const float4*)(Brow + 0);
    float4 pb1 = *(const float4*)(Brow + 4);

    ull acc[4][8];
    #pragma unroll
    for (int p=0;p<4;p++)
        #pragma unroll
        for (int j=0;j<8;j++) acc[p][j] = 0ULL;

    #pragma unroll 1
    for (int kt=0; kt<128; kt+=16){
        const int buf = (kt >> 4) & 1;
        Ash[buf][sq+0][sr]=pa0.x; Ash[buf][sq+1][sr]=pa0.y;
        Ash[buf][sq+2][sr]=pa0.z; Ash[buf][sq+3][sr]=pa0.w;
        Ash[buf][sq+4][sr]=pa1.x; Ash[buf][sq+5][sr]=pa1.y;
        Ash[buf][sq+6][sr]=pa1.z; Ash[buf][sq+7][sr]=pa1.w;
        Bsh[buf][sq+0][sr]=pb0.x; Bsh[buf][sq+1][sr]=pb0.y;
        Bsh[buf][sq+2][sr]=pb0.z; Bsh[buf][sq+3][sr]=pb0.w;
        Bsh[buf][sq+4][sr]=pb1.x; Bsh[buf][sq+5][sr]=pb1.y;
        Bsh[buf][sq+6][sr]=pb1.z; Bsh[buf][sq+7][sr]=pb1.w;
        __syncthreads();
        if (kt + 16 < 128){
            pa0 = *(const float4*)(Arow + kt + 16);
            pa1 = *(const float4*)(Arow + kt + 20);
            pb0 = *(const float4*)(Brow + kt + 16);
            pb1 = *(const float4*)(Brow + kt + 20);
        }
        #pragma unroll 8
        for (int k=0;k<16;k++){
            ulonglong2 a01 = *(const ulonglong2*)&Ash[buf][k][ty*8];
            ulonglong2 a23 = *(const ulonglong2*)&Ash[buf][k][ty*8+4];
            float4 b0 = *(const float4*)&Bsh[buf][k][tx*8];
            float4 b1 = *(const float4*)&Bsh[buf][k][tx*8+4];
            ull bb0=pack2(b0.x,b0.x), bb1=pack2(b0.y,b0.y);
            ull bb2=pack2(b0.z,b0.z), bb3=pack2(b0.w,b0.w);
            ull bb4=pack2(b1.x,b1.x), bb5=pack2(b1.y,b1.y);
            ull bb6=pack2(b1.z,b1.z), bb7=pack2(b1.w,b1.w);
            fma2(acc[0][0],a01.x,bb0); fma2(acc[0][1],a01.x,bb1);
            fma2(acc[0][2],a01.x,bb2); fma2(acc[0][3],a01.x,bb3);
            fma2(acc[0][4],a01.x,bb4); fma2(acc[0][5],a01.x,bb5);
            fma2(acc[0][6],a01.x,bb6); fma2(acc[0][7],a01.x,bb7);
            fma2(acc[1][0],a01.y,bb0); fma2(acc[1][1],a01.y,bb1);
            fma2(acc[1][2],a01.y,bb2); fma2(acc[1][3],a01.y,bb3);
            fma2(acc[1][4],a01.y,bb4); fma2(acc[1][5],a01.y,bb5);
            fma2(acc[1][6],a01.y,bb6); fma2(acc[1][7],a01.y,bb7);
            fma2(acc[2][0],a23.x,bb0); fma2(acc[2][1],a23.x,bb1);
            fma2(acc[2][2],a23.x,bb2); fma2(acc[2][3],a23.x,bb3);
            fma2(acc[2][4],a23.x,bb4); fma2(acc[2][5],a23.x,bb5);
            fma2(acc[2][6],a23.x,bb6); fma2(acc[2][7],a23.x,bb7);
            fma2(acc[3][0],a23.y,bb0); fma2(acc[3][1],a23.y,bb1);
            fma2(acc[3][2],a23.y,bb2); fma2(acc[3][3],a23.y,bb3);
            fma2(acc[3][4],a23.y,bb4); fma2(acc[3][5],a23.y,bb5);
            fma2(acc[3][6],a23.y,bb6); fma2(acc[3][7],a23.y,bb7);
        }
        __syncthreads();
    }
    #pragma unroll
    for (int j=0;j<8;j++){
        const int c = cb + tx*8 + j;
        // planar: S/G plane + chain plane + feature
        const int aoff = (c & 256) + ((c >> 7) & 1)*128 + (c & 127);
        const float bias = (c < 256) ? (bl[c] + bce[c]) : 0.f;
        #pragma unroll
        for (int p=0;p<4;p++){
            float lo, hi; unpack2(acc[p][j], lo, hi);
            const int row = rb + ty*8 + 2*p;
            g_SG[(size_t)row*512 + aoff]     = lo + bias;
            g_SG[(size_t)(row+1)*512 + aoff] = hi + bias;
        }
    }
}

// -------- fused conv: warp-aligned chain split (warps 0-3 filter, 4-7 core) --------
#define NPB 16
__global__ __launch_bounds__(256,2)
void conv_kernel(const float* __restrict__ nf_in, float* __restrict__ nf_out,
                 const float* __restrict__ ef, const int* __restrict__ eidx,
                 const float* __restrict__ Wce, const float* __restrict__ alphap,
                 int blk_off){
    __shared__ __align__(16) float ef_sh[2][Mm][44];
    __shared__ int   idx_sh[2][Mm];
    __shared__ float fil_sh[Mm][128];
    const int t = threadIdx.x;          // 0..255
    const int w = t >> 5;
    const int lane = t & 31;
    const int chain = w >> 2;           // warp-uniform: 0=filter, 1=core
    const int o = (w & 3)*32 + lane;    // 0..127

    ull w2[22];
    const float* wrow = Wce + (o + chain*128)*44;
    #pragma unroll
    for (int i=0;i<22;i++){
        float2 wv = *(const float2*)(wrow + 2*i);
        w2[i] = pack2(wv.x, wv.y);
    }
    const float alpha = alphap[0];
    const int node0 = (blockIdx.x + blk_off) * NPB;

    if (t < 2*Mm*3){
        int bb = t/(Mm*3); int r = t - bb*(Mm*3); int m = r/3; int k = 41 + (r - m*3);
        ef_sh[bb][m][k] = 0.f;
    }
    {   // stage node0 -> buf 0
        const float* src = ef + (size_t)node0*(Mm*OEF);
        for (int e=t; e<Mm*OEF; e+=256){ int m=e/OEF, k=e-m*OEF; ef_sh[0][m][k]=src[e]; }
        if (t < Mm) idx_sh[0][t] = eidx[node0*Mm + t];
    }
    __syncthreads();

    for (int i=0;i<NPB;i++){
        const int node = node0 + i;
        const int buf  = i & 1;
        const int b    = node >> 8;

        float pf0=0.f, pf1=0.f, pf2=0.f; int pidx=0;
        const bool hasnext = (i+1 < NPB);
        if (hasnext){
            const float* src = ef + (size_t)(node+1)*(Mm*OEF);
            pf0 = src[t]; pf1 = src[t+256];
            if (t+512 < Mm*OEF) pf2 = src[t+512];
            if (t < Mm) pidx = eidx[(node+1)*Mm + t];
        }

        const float* base = g_SG + (size_t)b*Nn*512 + 256 + chain*128 + o;
        const float sP = g_SG[(size_t)node*512 + chain*128 + o];

        int jq[4]; float gq[4];
        #pragma unroll
        for (int q=0;q<4;q++){
            jq[q] = idx_sh[buf][q];
            gq[q] = base[(size_t)(jq[q] < 0 ? 0 : jq[q])*512];
        }
        float sp[Mm];                   // live only in core warps
        #pragma unroll 1
        for (int mb=0; mb<Mm; mb+=4){
            int jn[4]={0,0,0,0}; float gn[4]={0.f,0.f,0.f,0.f};
            if (mb+4 < Mm){
                #pragma unroll
                for (int q=0;q<4;q++){
                    jn[q] = idx_sh[buf][mb+4+q];
                    gn[q] = base[(size_t)(jn[q] < 0 ? 0 : jn[q])*512];
                }
            }
            #pragma unroll
            for (int q=0;q<4;q++){
                ull a0 = 0ULL, a1 = 0ULL;
                const ulonglong2* e2p = (const ulonglong2*)ef_sh[buf][mb+q];
                #pragma unroll
                for (int p=0;p<5;p++){
                    ulonglong2 ev  = e2p[2*p];
                    ulonglong2 ev2 = e2p[2*p+1];
                    fma2(a0, ev.x,  w2[4*p+0]); fma2(a1, ev.y,  w2[4*p+1]);
                    fma2(a0, ev2.x, w2[4*p+2]); fma2(a1, ev2.y, w2[4*p+3]);
                }
                { ulonglong2 ev = e2p[10];
                  fma2(a0, ev.x, w2[20]); fma2(a1, ev.y, w2[21]); }
                float lo, hi; unpack2(add2(a0, a1), lo, hi);
                const float gv = lo + hi + sP + gq[q];
                if (chain == 0){
                    fil_sh[mb+q][o] = (jq[q] >= 0) ? sigm(gv) : 0.f;
                } else {
                    sp[mb+q] = softplusf(gv);
                }
            }
            #pragma unroll
            for (int q=0;q<4;q++){ jq[q]=jn[q]; gq[q]=gn[q]; }
        }
        __syncthreads();                 // fil_sh ready
        if (chain == 1){
            float accum = 0.f;
            #pragma unroll
            for (int m=0;m<Mm;m++) accum += fil_sh[m][o] * sp[m];
            nf_out[(size_t)node*NF + o] =
                softplusf(alpha * nf_in[(size_t)node*NF + o] + accum);
        }
        if (hasnext){
            const int nb = buf ^ 1;
            { int e=t;     int m=e/OEF, k=e-m*OEF; ef_sh[nb][m][k]=pf0; }
            { int e=t+256; int m=e/OEF, k=e-m*OEF; ef_sh[nb][m][k]=pf1; }
            if (t+512 < Mm*OEF){ int e=t+512; int m=e/OEF, k=e-m*OEF; ef_sh[nb][m][k]=pf2; }
            if (t < Mm) idx_sh[nb][t] = pidx;
        }
        __syncthreads();
    }
}

// -------- output --------
__global__ void out_kernel(float* __restrict__ out){
    __shared__ float DS[32*33];
    __shared__ float NS[32*65];
    const int t  = threadIdx.x;
    const int it = blockIdx.x;
    const int b  = blockIdx.y;
    const int i_l = t & 31;
    const int fg  = t >> 5;
    float acc[8];
    #pragma unroll
    for (int f=0;f<8;f++) acc[f]=0.f;

    for (int jt=0; jt<8; jt++){
        #pragma unroll
        for (int i=0;i<4;i++){
            int e = t + i*256; int r = e>>5; int c = e&31;
            DS[r*33+c] = g_DA[(it*32+r)*Nn + jt*32 + c];
        }
        #pragma unroll
        for (int i=0;i<8;i++){
            int e = t + i*256; int j = e>>6; int f = e&63;
            NS[j*65+f] = g_fin[(b*Nn + jt*32 + j)*EF + f];
        }
        __syncthreads();
        #pragma unroll
        for (int j=0;j<32;j++){
            float d = DS[i_l*33 + j];
            #pragma unroll
            for (int f=0;f<8;f++) acc[f] += d * NS[j*65 + fg*8 + f];
        }
        __syncthreads();
    }
    const int i = it*32 + i_l;
    float* orow = out + (size_t)(b*Nn + i)*128;
    #pragma unroll
    for (int f=0;f<8;f++) orow[64 + fg*8 + f] = acc[f];
    for (int e=t; e<32*64; e+=256){
        int r = e>>6; int f = e&63;
        out[(size_t)(b*Nn + it*32 + r)*128 + f] = g_fin[(b*Nn + it*32 + r)*EF + f];
    }
}

extern "C" void kernel_launch(void* const* d_in, const int* in_sizes, int n_in,
                              void* d_out, int out_size){
    const float* node_fea = (const float*)d_in[0];
    const float* edge_fea = (const float*)d_in[1];
    const int*   eidx     = (const int*)  d_in[2];
    const float* dis      = (const float*)d_in[3];
    const float* Wn  = (const float*)d_in[4];
    const float* bn  = (const float*)d_in[5];
    const float* We  = (const float*)d_in[6];
    const float* be  = (const float*)d_in[7];
    const float* W1  = (const float*)d_in[8];
    const float* b1  = (const float*)d_in[9];
    const float* a1  = (const float*)d_in[10];
    const float* W2  = (const float*)d_in[11];
    const float* b2  = (const float*)d_in[12];
    const float* a2  = (const float*)d_in[13];
    const float* W3  = (const float*)d_in[14];
    const float* b3  = (const float*)d_in[15];
    const float* a3  = (const float*)d_in[16];
    const float* Wf  = (const float*)d_in[17];
    const float* bf  = (const float*)d_in[18];
    const float* DAw = (const float*)d_in[19];
    const float* DAb = (const float*)d_in[20];
    float* out = (float*)d_out;

    float *nfA, *nfB, *bceP, *WceP, *finP;
    cudaGetSymbolAddress((void**)&nfA,  g_nfA);
    cudaGetSymbolAddress((void**)&nfB,  g_nfB);
    cudaGetSymbolAddress((void**)&bceP, g_bce);
    cudaGetSymbolAddress((void**)&WceP, g_Wce);
    cudaGetSymbolAddress((void**)&finP, g_fin);

    const float* Ws[3] = {W1,W2,W3};
    const float* bs[3] = {b1,b2,b3};
    const float* as[3] = {a1,a2,a3};
    const int NBLK = ROWS/NPB;   // 1024

    // launches 1-3: prerequisites; launches 4,5,6: conv layer-1 chunks
    linear_kernel<ONF,NF,8><<<ROWS/8, NF>>>(node_fea, Wn, bn, nfA);          // 1
    wce_kernel<<<dim3(256,3), 64>>>(W1, W2, W3, We, be);                     // 2
    sg_kernel<<<dim3(ROWS/128, 4), 256>>>(nfA, W1, b1, bceP);                // 3
    conv_kernel<<<NBLK/3, 256>>>(nfA, nfB, edge_fea, eidx, WceP, as[0], 0);                 // 4
    conv_kernel<<<NBLK/3, 256>>>(nfA, nfB, edge_fea, eidx, WceP, as[0], NBLK/3);            // 5
    conv_kernel<<<NBLK - 2*(NBLK/3), 256>>>(nfA, nfB, edge_fea, eidx, WceP, as[0], 2*(NBLK/3)); // 6
    da_kernel<<<128, 256>>>(dis, DAw, DAb, 0);
    da_kernel<<<128, 256>>>(dis, DAw, DAb, 128);

    float* nin  = nfB;
    float* nout = nfA;
    for (int l=1; l<3; l++){
        sg_kernel<<<dim3(ROWS/128, 4), 256>>>(nin, Ws[l], bs[l], bceP + l*256);
        conv_kernel<<<NBLK, 256>>>(nin, nout, edge_fea, eidx,
                                   WceP + (size_t)l*256*44, as[l], 0);
        float* tmp = nin; nin = nout; nout = tmp;
    }

    linear_kernel<NF,EF,16><<<ROWS/16, EF>>>(nin, Wf, bf, finP);
    out_kernel<<<dim3(8, Bn), 256>>>(out);
}